// round 1
// baseline (speedup 1.0000x reference)
#include <cuda_runtime.h>
#include <math.h>

// -------- scratch: ll_ref [16,3,128,128] fp32 (3 MB) --------
__device__ float g_ll[16 * 3 * 128 * 128];

// =====================================================================
// Kernel 1: 3x3 conv (Cin=64 -> Cout=3, pad=1) + bias + tanh
// Grid: (4,4,16) blocks of (32,32) threads. Each block = one 32x32 tile.
// =====================================================================
__global__ __launch_bounds__(1024, 2)
void conv_tanh_kernel(const float* __restrict__ fused,
                      const float* __restrict__ wgt,    // [3,64,3,3]
                      const float* __restrict__ bias,   // [3]
                      float* __restrict__ ll)           // [16,3,128,128]
{
    __shared__ float sw[3 * 64 * 9];   // 6912 B
    __shared__ float st[34][34];       // input tile with halo

    const int b   = blockIdx.z;
    const int ty0 = blockIdx.y * 32;
    const int tx0 = blockIdx.x * 32;
    const int tx  = threadIdx.x;
    const int ty  = threadIdx.y;
    const int tid = ty * 32 + tx;

    // stage all weights into shared once
    for (int i = tid; i < 3 * 64 * 9; i += 1024) sw[i] = wgt[i];

    float acc0 = 0.f, acc1 = 0.f, acc2 = 0.f;
    const float* fb = fused + (size_t)b * 64 * 128 * 128;

    for (int c = 0; c < 64; ++c) {
        __syncthreads();   // protect previous iter's reads AND (iter 0) weight load
        // load 34x34 halo tile for channel c (zero-padded)
        for (int i = tid; i < 34 * 34; i += 1024) {
            int ly = i / 34, lx = i - ly * 34;
            int gy = ty0 - 1 + ly, gx = tx0 - 1 + lx;
            float v = 0.f;
            if ((unsigned)gy < 128u && (unsigned)gx < 128u)
                v = fb[(c * 128 + gy) * 128 + gx];
            st[ly][lx] = v;
        }
        __syncthreads();

        const float* w0 = sw + (0 * 64 + c) * 9;
        const float* w1 = sw + (1 * 64 + c) * 9;
        const float* w2 = sw + (2 * 64 + c) * 9;
        #pragma unroll
        for (int ky = 0; ky < 3; ++ky) {
            #pragma unroll
            for (int kx = 0; kx < 3; ++kx) {
                float v = st[ty + ky][tx + kx];
                int k = ky * 3 + kx;
                acc0 = fmaf(v, w0[k], acc0);
                acc1 = fmaf(v, w1[k], acc1);
                acc2 = fmaf(v, w2[k], acc2);
            }
        }
    }

    const int oy = ty0 + ty, ox = tx0 + tx;
    size_t base = ((size_t)b * 3) * (128 * 128) + (size_t)oy * 128 + ox;
    ll[base]                 = tanhf(acc0 + bias[0]);
    ll[base + 128 * 128]     = tanhf(acc1 + bias[1]);
    ll[base + 2 * 128 * 128] = tanhf(acc2 + bias[2]);
}

// =====================================================================
// Kernel 2: fused double inverse-Haar.
// One thread per 256-level pixel; recomputes curr from (ll, hf2), then
// expands with hf1 into a 2x2 block of the 512-level output.
// Grid: (1, 256, 48), block 256 (threadIdx.x == w256).
// =====================================================================
__global__ __launch_bounds__(256)
void iwt2_kernel(const float* __restrict__ ll,    // [16,3,128,128]
                 const float* __restrict__ hf1,   // [16,9,256,256]
                 const float* __restrict__ hf2,   // [16,9,128,128]
                 float* __restrict__ out)         // [16,3,512,512]
{
    const int w256 = threadIdx.x;          // 0..255
    const int h256 = blockIdx.y;           // 0..255
    const int bc   = blockIdx.z;           // b*3 + c, 0..47
    const int b = bc / 3, c = bc - 3 * b;

    const int h128 = h256 >> 1, w128 = w256 >> 1;
    const float sp = (h256 & 1) ? 1.f : -1.f;
    const float sq = (w256 & 1) ? 1.f : -1.f;

    // level-1 synthesis: curr(h256, w256)
    const float L = ll[((size_t)bc * 128 + h128) * 128 + w128];
    size_t h2b = (((size_t)b * 9 + 3 * c) * 128 + h128) * 128 + w128;
    const float lh = hf2[h2b]                 * 2.f - 1.f;
    const float hl = hf2[h2b + 128 * 128]     * 2.f - 1.f;
    const float hh = hf2[h2b + 2 * 128 * 128] * 2.f - 1.f;
    const float curr = 0.5f * (L + sp * lh + sq * hl + (sp * sq) * hh);

    // level-2 synthesis: 2x2 output block
    size_t h1b = (((size_t)b * 9 + 3 * c) * 256 + h256) * 256 + w256;
    const float a  = hf1[h1b]                 * 2.f - 1.f;
    const float bb = hf1[h1b + 256 * 256]     * 2.f - 1.f;
    const float cc = hf1[h1b + 2 * 256 * 256] * 2.f - 1.f;

    const float o00 = 0.5f * (curr - a - bb + cc);
    const float o01 = 0.5f * (curr - a + bb - cc);
    const float o10 = 0.5f * (curr + a - bb - cc);
    const float o11 = 0.5f * (curr + a + bb + cc);

    size_t ob = (((size_t)bc * 512) + 2 * (size_t)h256) * 512 + 2 * w256;
    *reinterpret_cast<float2*>(out + ob)       = make_float2(o00, o01);
    *reinterpret_cast<float2*>(out + ob + 512) = make_float2(o10, o11);
}

// =====================================================================
extern "C" void kernel_launch(void* const* d_in, const int* in_sizes, int n_in,
                              void* d_out, int out_size)
{
    const float* fused  = (const float*)d_in[0];  // [16,64,128,128]
    const float* hf1    = (const float*)d_in[1];  // [16,9,256,256]
    const float* hf2    = (const float*)d_in[2];  // [16,9,128,128]
    const float* conv_w = (const float*)d_in[3];  // [3,64,3,3]
    const float* conv_b = (const float*)d_in[4];  // [3]
    float* out = (float*)d_out;                   // [16,3,512,512]

    float* ll_ptr;
    cudaGetSymbolAddress((void**)&ll_ptr, g_ll);

    dim3 g1(4, 4, 16), b1(32, 32);
    conv_tanh_kernel<<<g1, b1>>>(fused, conv_w, conv_b, ll_ptr);

    dim3 g2(1, 256, 48), b2(256);
    iwt2_kernel<<<g2, b2>>>(ll_ptr, hf1, hf2, out);
}

// round 2
// speedup vs baseline: 2.0272x; 2.0272x over previous
#include <cuda_runtime.h>
#include <math.h>

// ---------------- scratch ----------------
// partial conv sums: [cg=4][b=16][co=3][128][128]
__device__ float  g_part[4 * 16 * 3 * 128 * 128];
// prepacked channel-pair weights: [co=3][cp=32][k=9] float2 = (w[c0],w[c1])
__device__ float2 g_wp[3 * 32 * 9];

// ---------------- f32x2 helpers ----------------
__device__ __forceinline__ void ffma2(unsigned long long& d,
                                      unsigned long long a,
                                      unsigned long long b) {
    asm("fma.rn.f32x2 %0, %1, %2, %0;" : "+l"(d) : "l"(a), "l"(b));
}
__device__ __forceinline__ unsigned long long pk2(float lo, float hi) {
    unsigned long long r;
    asm("mov.b64 %0, {%1, %2};" : "=l"(r) : "f"(lo), "f"(hi));
    return r;
}
__device__ __forceinline__ float sum2(unsigned long long v) {
    float a, b;
    asm("mov.b64 {%0, %1}, %2;" : "=f"(a), "=f"(b) : "l"(v));
    return a + b;
}

// =====================================================================
// Kernel 0: prepack weight channel-pairs
// =====================================================================
__global__ void prep_w(const float* __restrict__ w) {
    int i = blockIdx.x * 256 + threadIdx.x;
    if (i < 3 * 32 * 9) {
        int co = i / 288;
        int rem = i - co * 288;
        int cp = rem / 9;
        int k  = rem - cp * 9;
        g_wp[i] = make_float2(w[(co * 64 + 2 * cp) * 9 + k],
                              w[(co * 64 + 2 * cp + 1) * 9 + k]);
    }
}

// =====================================================================
// Kernel 1: partial 3x3 conv, channel-pair f32x2.
// Grid (16 tiles, 16 batch, 4 channel-groups), block 256.
// Thread: 4 horizontal px (row ty, cols 4*tx8 .. +3), 16 channels (8 pairs).
// =====================================================================
#define HALO  34
#define PITCH 35   // PITCH % 4 == 3  -> conflict-free rows within a warp

__global__ __launch_bounds__(256, 3)
void conv_part(const float* __restrict__ fused) {
    __shared__ float  sv[4][HALO][PITCH];   // 4 staged channels
    __shared__ float2 swp[3 * 8 * 9];       // this cg's weight pairs

    const int tile = blockIdx.x;          // 0..15
    const int b    = blockIdx.y;          // 0..15
    const int cg   = blockIdx.z;          // 0..3
    const int tlx  = (tile & 3) * 32;
    const int tly  = (tile >> 2) * 32;
    const int t    = threadIdx.x;
    const int tx8  = t & 7;               // px cols 4*tx8 .. 4*tx8+3
    const int ty   = t >> 3;              // px row

    // stage this cg's weight pairs: swp[(co*8+j)*9+k] = g_wp[(co*32+cg*8+j)*9+k]
    for (int i = t; i < 3 * 8 * 9; i += 256) {
        int co  = i / 72;
        int rem = i - co * 72;
        swp[i] = g_wp[(co * 32 + cg * 8) * 9 + rem];
    }
    const unsigned long long* swp64 = reinterpret_cast<const unsigned long long*>(swp);

    unsigned long long acc[4][3];   // [px][co], lanes = channel pair halves
    #pragma unroll
    for (int p = 0; p < 4; ++p)
        #pragma unroll
        for (int co = 0; co < 3; ++co) acc[p][co] = 0ull;

    const float* fb = fused + ((size_t)b * 64 + cg * 16) * (128 * 128);
    const int c0 = 4 * tx8;

    for (int s = 0; s < 4; ++s) {         // 4 stages x 4 channels
        __syncthreads();
        // batched halo load: 4 channels x 34x34 (zero padded)
        for (int i = t; i < 4 * HALO * HALO; i += 256) {
            int ch  = i / (HALO * HALO);
            int rem = i - ch * (HALO * HALO);
            int r = rem / HALO;
            int c = rem - r * HALO;
            int gy = tly - 1 + r, gx = tlx - 1 + c;
            float v = 0.f;
            if ((unsigned)gy < 128u && (unsigned)gx < 128u)
                v = fb[((s * 4 + ch) * 128 + gy) * 128 + gx];
            sv[ch][r][c] = v;
        }
        __syncthreads();

        #pragma unroll
        for (int cp = 0; cp < 2; ++cp) {  // 2 channel-pairs per stage
            // window: rows ty..ty+2, cols c0..c0+5, packed (chA, chB)
            unsigned long long pp[3][6];
            #pragma unroll
            for (int wr = 0; wr < 3; ++wr)
                #pragma unroll
                for (int cc = 0; cc < 6; ++cc)
                    pp[wr][cc] = pk2(sv[2 * cp][ty + wr][c0 + cc],
                                     sv[2 * cp + 1][ty + wr][c0 + cc]);

            const int wbase = (s * 2 + cp) * 9;
            #pragma unroll
            for (int co = 0; co < 3; ++co) {
                #pragma unroll
                for (int ky = 0; ky < 3; ++ky) {
                    #pragma unroll
                    for (int kx = 0; kx < 3; ++kx) {
                        unsigned long long w = swp64[(co * 8) * 9 + wbase + ky * 3 + kx];
                        ffma2(acc[0][co], pp[ky][kx + 0], w);
                        ffma2(acc[1][co], pp[ky][kx + 1], w);
                        ffma2(acc[2][co], pp[ky][kx + 2], w);
                        ffma2(acc[3][co], pp[ky][kx + 3], w);
                    }
                }
            }
        }
    }

    // epilogue: reduce lanes, store partials as float4
    const int oy = tly + ty, ox = tlx + c0;
    #pragma unroll
    for (int co = 0; co < 3; ++co) {
        float4 o;
        o.x = sum2(acc[0][co]);
        o.y = sum2(acc[1][co]);
        o.z = sum2(acc[2][co]);
        o.w = sum2(acc[3][co]);
        size_t idx = (((size_t)cg * 16 + b) * 3 + co) * (128 * 128) + (size_t)oy * 128 + ox;
        *reinterpret_cast<float4*>(&g_part[idx]) = o;
    }
}

// =====================================================================
// Kernel 2: combine partials + bias + tanh, then fused double IWT.
// Thread handles a 2x2 block at the 256-level (one shared 128-parent),
// producing a 4x4 block of the 512-level output.
// Grid (128, 48), block 128. t = w128, blockIdx.x = h128, blockIdx.y = b*3+c.
// =====================================================================
__global__ __launch_bounds__(128)
void iwt2_kernel(const float* __restrict__ hf1,   // [16,9,256,256]
                 const float* __restrict__ hf2,   // [16,9,128,128]
                 const float* __restrict__ bias,  // [3]
                 float* __restrict__ out)         // [16,3,512,512]
{
    const int t  = threadIdx.x;     // w128: 0..127
    const int H  = blockIdx.x;      // h128: 0..127
    const int bc = blockIdx.y;      // b*3+c
    const int b  = bc / 3, c = bc - 3 * b;

    // combine 4 conv partials + bias -> tanh
    size_t pidx = ((size_t)bc * 128 + H) * 128 + t;   // [b][co] == bc contiguous
    const size_t pstride = (size_t)16 * 3 * 128 * 128;
    float p = g_part[pidx] + g_part[pidx + pstride] +
              g_part[pidx + 2 * pstride] + g_part[pidx + 3 * pstride];
    const float ll = tanhf(p + bias[c]);

    // level-1 coefficients at (H, t)
    size_t h2b = (((size_t)b * 9 + 3 * c) * 128 + H) * 128 + t;
    const float lh = hf2[h2b]                 * 2.f - 1.f;
    const float hl = hf2[h2b + 128 * 128]     * 2.f - 1.f;
    const float hh = hf2[h2b + 2 * 128 * 128] * 2.f - 1.f;

    // curr 2x2 at 256-level
    float curr[2][2];
    #pragma unroll
    for (int dy = 0; dy < 2; ++dy) {
        float sp = dy ? 1.f : -1.f;
        #pragma unroll
        for (int dx = 0; dx < 2; ++dx) {
            float sq = dx ? 1.f : -1.f;
            curr[dy][dx] = 0.5f * (ll + sp * lh + sq * hl + (sp * sq) * hh);
        }
    }

    // level-2: hf1 pairs (cols 2t, 2t+1) for rows 2H, 2H+1, 3 channels
    size_t h1b = (((size_t)b * 9 + 3 * c) * 256 + 2 * (size_t)H) * 256 + 2 * t;
    const size_t cs = (size_t)256 * 256;
    float2 A0 = *reinterpret_cast<const float2*>(hf1 + h1b);
    float2 B0 = *reinterpret_cast<const float2*>(hf1 + h1b + cs);
    float2 C0 = *reinterpret_cast<const float2*>(hf1 + h1b + 2 * cs);
    float2 A1 = *reinterpret_cast<const float2*>(hf1 + h1b + 256);
    float2 B1 = *reinterpret_cast<const float2*>(hf1 + h1b + cs + 256);
    float2 C1 = *reinterpret_cast<const float2*>(hf1 + h1b + 2 * cs + 256);

    size_t ob = ((size_t)bc * 512 + 4 * (size_t)H) * 512 + 4 * t;

    #pragma unroll
    for (int dy = 0; dy < 2; ++dy) {
        float2 Ap = dy ? A1 : A0;
        float2 Bp = dy ? B1 : B0;
        float2 Cp = dy ? C1 : C0;
        float4 row0, row1;   // output rows 4H+2dy, 4H+2dy+1 (cols 4t..4t+3)
        #pragma unroll
        for (int dx = 0; dx < 2; ++dx) {
            float a  = (dx ? Ap.y : Ap.x) * 2.f - 1.f;
            float bb = (dx ? Bp.y : Bp.x) * 2.f - 1.f;
            float cc = (dx ? Cp.y : Cp.x) * 2.f - 1.f;
            float cu = curr[dy][dx];
            float o00 = 0.5f * (cu - a - bb + cc);
            float o01 = 0.5f * (cu - a + bb - cc);
            float o10 = 0.5f * (cu + a - bb - cc);
            float o11 = 0.5f * (cu + a + bb + cc);
            if (dx == 0) { row0.x = o00; row0.y = o01; row1.x = o10; row1.y = o11; }
            else         { row0.z = o00; row0.w = o01; row1.z = o10; row1.w = o11; }
        }
        *reinterpret_cast<float4*>(out + ob + (size_t)(2 * dy) * 512)     = row0;
        *reinterpret_cast<float4*>(out + ob + (size_t)(2 * dy + 1) * 512) = row1;
    }
}

// =====================================================================
extern "C" void kernel_launch(void* const* d_in, const int* in_sizes, int n_in,
                              void* d_out, int out_size)
{
    const float* fused  = (const float*)d_in[0];  // [16,64,128,128]
    const float* hf1    = (const float*)d_in[1];  // [16,9,256,256]
    const float* hf2    = (const float*)d_in[2];  // [16,9,128,128]
    const float* conv_w = (const float*)d_in[3];  // [3,64,3,3]
    const float* conv_b = (const float*)d_in[4];  // [3]
    float* out = (float*)d_out;                   // [16,3,512,512]

    prep_w<<<4, 256>>>(conv_w);

    dim3 g1(16, 16, 4);
    conv_part<<<g1, 256>>>(fused);

    dim3 g2(128, 48);
    iwt2_kernel<<<g2, 128>>>(hf1, hf2, conv_b, out);
}